// round 8
// baseline (speedup 1.0000x reference)
#include <cuda_runtime.h>
#include <cuda_bf16.h>

// Balloon-Windkessel BOLD, explicit Euler, T=1000 steps, B=16384 sims.
// R8 = R7 (53.5us) with the readout software-pipelined one full step:
//  - rv = rcp.approx(v2) issues right after v2 is produced; y + STG are
//    emitted at the top of the NEXT step -> MUFU latency fully hidden,
//    STG no longer serializes the step tail.
//  - G(u) evaluated pairwise-Horner (same 8 FMA, depth 24 vs 36).
//  - state recurrences bit-identical to R7 (rel_err 1.14e-4 path).
// Warp count is hard-capped at 512 (1/SMSP); per-warp schedule is the
// only lever. Time-segmentation was analyzed and abandoned: corrections
// cost >= recomputation and perturb carried rounding (R2 failure mode).

#define DT_C        0.01f
#define V0_C        0.02f
#define NOISE_AMP_C 0.01f
#define BATCH_C     16384

__device__ float bw_scratch;   // sink for the one spurious prologue store

__device__ __forceinline__ float fast_rcp(float x) {
    float r; asm("rcp.approx.f32 %0, %1;" : "=f"(r) : "f"(x)); return r;
}

struct BWState {
    float s, f, v, q;
    float G;    // f*E(f)/beta for current f (staged one step ahead)
    float in1;  // fma(-mu, f-1, -sigma*s)  (s-drive, staged)
};

struct BWConst {
    float sigma, mu, c_vl;
    float C0, C1, C2, C3;            // readout constants
    float g0,g1,g2,g3,g4,g5,g6,g7;   // G(u) Taylor coefficients
};

// State-update front; staging for next step. Carried arithmetic == R7.
__device__ __forceinline__ void bw_front(BWState& st, const BWConst& C, float z)
{
    const float s2 = fmaf(DT_C, fmaf(NOISE_AMP_C, z, st.in1), st.s);
    const float f2 = fmaf(DT_C, st.s, st.f);
    const float v2 = fmaf(C.c_vl, st.f - st.v, st.v);
    const float q2 = fmaf(C.c_vl, st.G - st.q, st.q);

    const float u  = f2 - 1.0f;
    // degree-7 pairwise Horner (8 FMA, shallow)
    const float u2  = u * u;
    const float p01 = fmaf(C.g1, u, C.g0);
    const float p23 = fmaf(C.g3, u, C.g2);
    const float p45 = fmaf(C.g5, u, C.g4);
    const float p67 = fmaf(C.g7, u, C.g6);
    float p = fmaf(p67, u2, p45);
    p       = fmaf(p,   u2, p23);
    st.G    = fmaf(p,   u2, p01);
    st.in1  = fmaf(-C.mu, u, -C.sigma * s2);

    st.s = s2; st.f = f2; st.v = v2; st.q = q2;
}

// Readout of a PENDING (previous) step; rv already computed last step.
__device__ __forceinline__ float bw_readout(const BWConst& C,
                                            float pv, float pq, float prv)
{
    const float t0 = fmaf(-C.C3, pv, C.C0);
    const float t1 = fmaf(-C.C1, pq, t0);
    return fmaf(-C.C2 * pq, prv, t1);
}

template<int U, int BS>
__global__ __launch_bounds__(128, 1)
void bw_bold_kernel(const float* __restrict__ noise,
                    const float* __restrict__ sigma_p,
                    const float* __restrict__ mu_p,
                    const float* __restrict__ lamb_p,
                    const float* __restrict__ beta_p,
                    const float* __restrict__ psi_p,
                    const float* __restrict__ phi_p,
                    const float* __restrict__ chi_p,
                    float* __restrict__ out,
                    int T)
{
    const int gid = blockIdx.x * blockDim.x + threadIdx.x;

    BWConst C;
    C.sigma = __ldg(sigma_p);
    C.mu    = __ldg(mu_p);
    const float lamb = __ldg(lamb_p);
    const float beta = __ldg(beta_p);
    const float psi  = __ldg(psi_p);
    const float phi  = __ldg(phi_p);
    const float chi  = __ldg(chi_p);
    C.c_vl  = DT_C / lamb;
    C.C0    = V0_C * (phi + psi + chi);
    C.C1    = V0_C * phi;
    C.C2    = V0_C * psi;
    C.C3    = V0_C * chi;

    // One-time double-precision Taylor coefficients for
    // G(u) = (1+u)*E(1+u)/beta, E(f)=1-exp(ln(1-beta)/f).
    {
        const double bd  = (double)beta;
        const double c   = log(1.0 - bd);
        const double omb = 1.0 - bd;
        double a[8], A[8], e[8];
        a[0] = 0.0;
        #pragma unroll
        for (int k = 1; k < 8; k++) a[k] = (k & 1) ? -c : c;
        A[0] = 1.0;
        #pragma unroll
        for (int k = 0; k < 7; k++) {
            double sum = 0.0;
            #pragma unroll
            for (int j = 0; j <= k; j++) sum += (double)(j + 1) * a[j + 1] * A[k - j];
            A[k + 1] = sum / (double)(k + 1);
        }
        e[0] = 1.0 - omb * A[0];
        #pragma unroll
        for (int k = 1; k < 8; k++) e[k] = -omb * A[k];
        const double ibd = 1.0 / bd;
        C.g0 = (float)(e[0] * ibd);
        C.g1 = (float)((e[1] + e[0]) * ibd);
        C.g2 = (float)((e[2] + e[1]) * ibd);
        C.g3 = (float)((e[3] + e[2]) * ibd);
        C.g4 = (float)((e[4] + e[3]) * ibd);
        C.g5 = (float)((e[5] + e[4]) * ibd);
        C.g6 = (float)((e[6] + e[5]) * ibd);
        C.g7 = (float)((e[7] + e[6]) * ibd);
    }

    BWState st;
    st.s = 0.0f; st.f = 1.0f; st.v = 1.0f; st.q = 1.0f;
    {
        // seed staged values for step 0 (u = 0)
        st.G   = C.g0;
        st.in1 = fmaf(-C.mu, 0.0f, -C.sigma * 0.0f);
    }

    const float* np = noise + gid;
    float*       op = out   + gid;

    // Pipelined readout state: the prologue's spurious store goes to scratch.
    float  pend_v    = st.v;
    float  pend_q    = st.q;
    float  pend_rv   = fast_rcp(st.v);
    float* pend_addr = &bw_scratch;

    const int nch = T / U;

    float bufA[U], bufB[U];
    if (nch > 0) {
        #pragma unroll
        for (int i = 0; i < U; i++) bufA[i] = np[(size_t)i * BS];
    }

    int c = 0;
    for (; c + 1 < nch; c += 2) {
        {   // prefetch chunk c+1
            const float* pp = np + (size_t)(c + 1) * U * BS;
            #pragma unroll
            for (int i = 0; i < U; i++) bufB[i] = pp[(size_t)i * BS];
        }
        {   // compute chunk c
            float* o = op + (size_t)c * U * BS;
            #pragma unroll
            for (int i = 0; i < U; i++) {
                *pend_addr = bw_readout(C, pend_v, pend_q, pend_rv);
                bw_front(st, C, bufA[i]);
                pend_v = st.v; pend_q = st.q;
                pend_rv = fast_rcp(st.v);
                pend_addr = o + (size_t)i * BS;
            }
        }
        if (c + 2 < nch) {   // prefetch chunk c+2
            const float* pp = np + (size_t)(c + 2) * U * BS;
            #pragma unroll
            for (int i = 0; i < U; i++) bufA[i] = pp[(size_t)i * BS];
        }
        {   // compute chunk c+1
            float* o = op + (size_t)(c + 1) * U * BS;
            #pragma unroll
            for (int i = 0; i < U; i++) {
                *pend_addr = bw_readout(C, pend_v, pend_q, pend_rv);
                bw_front(st, C, bufB[i]);
                pend_v = st.v; pend_q = st.q;
                pend_rv = fast_rcp(st.v);
                pend_addr = o + (size_t)i * BS;
            }
        }
    }
    if (c < nch) {  // odd trailing chunk
        float* o = op + (size_t)c * U * BS;
        #pragma unroll
        for (int i = 0; i < U; i++) {
            *pend_addr = bw_readout(C, pend_v, pend_q, pend_rv);
            bw_front(st, C, bufA[i]);
            pend_v = st.v; pend_q = st.q;
            pend_rv = fast_rcp(st.v);
            pend_addr = o + (size_t)i * BS;
        }
        c++;
    }

    // Tail (T not divisible by U).
    for (int t = nch * U; t < T; t++) {
        *pend_addr = bw_readout(C, pend_v, pend_q, pend_rv);
        bw_front(st, C, np[(size_t)t * BS]);
        pend_v = st.v; pend_q = st.q;
        pend_rv = fast_rcp(st.v);
        pend_addr = op + (size_t)t * BS;
    }

    // Flush the final pending readout.
    *pend_addr = bw_readout(C, pend_v, pend_q, pend_rv);
}

extern "C" void kernel_launch(void* const* d_in, const int* in_sizes, int n_in,
                              void* d_out, int out_size)
{
    const float* noise = (const float*)d_in[0];
    const int T = in_sizes[0] / BATCH_C;

    const int threads = 128;
    const int blocks  = BATCH_C / threads;   // 128 blocks x 128 thr = 1 warp/SMSP

    bw_bold_kernel<20, BATCH_C><<<blocks, threads>>>(
        noise,
        (const float*)d_in[1], (const float*)d_in[2],
        (const float*)d_in[3], (const float*)d_in[4],
        (const float*)d_in[5], (const float*)d_in[6],
        (const float*)d_in[7],
        (float*)d_out, T);
}